// round 1
// baseline (speedup 1.0000x reference)
#include <cuda_runtime.h>
#include <math.h>

// ---------------------------------------------------------------------------
// SPDTransform: out_b = E_b (W^T Xp_b W) E_b^T,  E = reshape(silu(Y@W1+b1)@W2+b2)
//
// Restructured as:
//   W2'[m,64i+j] = sum_k W2[m,64i+k] * W[j,k]      (fold, per launch)
//   b2'[64i+j]   = sum_k b2[64i+k]   * W[j,k]
//   h  = silu(Y @ W1 + b1)                          [4096,4096]
//   Ft = h @ W2' + b2'   (row b reshapes to Ft_b = E_b W^T, [64,64])
//   out_b = Ft_b @ Xp_b @ Ft_b^T   with Xp = [[x,0],[0,I16]]
// ---------------------------------------------------------------------------

// Scratch (allocation-free rule: __device__ globals)
__device__ float g_h  [4096u * 4096u];
__device__ float g_W2p[4096u * 4096u];
__device__ float g_b2p[4096];

// ---- packed f32x2 helpers (B300: FFMA2 doubles fp32 FMA throughput) -------
__device__ __forceinline__ unsigned long long pack2(float x) {
    unsigned long long r;
    unsigned int xi = __float_as_uint(x);
    asm("mov.b64 %0, {%1, %1};" : "=l"(r) : "r"(xi));
    return r;
}
__device__ __forceinline__ unsigned long long fma2(unsigned long long a,
                                                   unsigned long long b,
                                                   unsigned long long c) {
    unsigned long long d;
    asm("fma.rn.f32x2 %0, %1, %2, %3;" : "=l"(d) : "l"(a), "l"(b), "l"(c));
    return d;
}
__device__ __forceinline__ float2 unpack2(unsigned long long v) {
    unsigned int lo, hi;
    asm("mov.b64 {%0, %1}, %2;" : "=r"(lo), "=r"(hi) : "l"(v));
    float2 f; f.x = __uint_as_float(lo); f.y = __uint_as_float(hi);
    return f;
}

// ---------------------------------------------------------------------------
// Generic 128x128 tile GEMM, BK=16, 256 threads, 8x8 per thread, f32x2 FMAs.
// C[M,N] = epi(A[M,K] @ B[K,N] + bias[N]).  lda=K, ldb=ldc=N.
// EPI==0: silu, EPI==1: bias only.
// ---------------------------------------------------------------------------
template <int EPI>
__global__ __launch_bounds__(256, 2)
void gemm128(const float* __restrict__ A, const float* __restrict__ B,
             const float* __restrict__ bias, float* __restrict__ C,
             int K, int N)
{
    __shared__ __align__(16) float As[2][16][132];  // transposed A tile (+pad)
    __shared__ __align__(16) float Bs[2][16][128];

    const int tid = threadIdx.x;
    const int tx  = tid & 15;
    const int ty  = tid >> 4;
    const long long Arow0 = (long long)blockIdx.y * 128;
    const int       Bcol0 = blockIdx.x * 128;

    // global load mapping
    const int arow = tid >> 2;         // 0..63  (rows arow, arow+64)
    const int ac   = (tid & 3) << 2;   // k-offset 0,4,8,12
    const int brow = tid >> 5;         // 0..7   (rows brow, brow+8)
    const int bc   = (tid & 31) << 2;  // col offset

    const float* Aptr = A + (Arow0 + arow) * (long long)K + ac;
    const float* Bptr = B + (long long)brow * N + Bcol0 + bc;
    const long long AstepRow = 64LL * K;
    const long long BstepRow = 8LL * N;

    unsigned long long acc[8][4];
#pragma unroll
    for (int i = 0; i < 8; ++i)
#pragma unroll
        for (int j = 0; j < 4; ++j) acc[i][j] = 0ull;

    const int nk = K >> 4;

    float4 a0 = *(const float4*)(Aptr);
    float4 a1 = *(const float4*)(Aptr + AstepRow);
    float4 b0 = *(const float4*)(Bptr);
    float4 b1 = *(const float4*)(Bptr + BstepRow);

    int buf = 0;
    // store tile 0 (A transposed)
    As[0][ac + 0][arow] = a0.x; As[0][ac + 1][arow] = a0.y;
    As[0][ac + 2][arow] = a0.z; As[0][ac + 3][arow] = a0.w;
    As[0][ac + 0][arow + 64] = a1.x; As[0][ac + 1][arow + 64] = a1.y;
    As[0][ac + 2][arow + 64] = a1.z; As[0][ac + 3][arow + 64] = a1.w;
    *(float4*)&Bs[0][brow][bc]     = b0;
    *(float4*)&Bs[0][brow + 8][bc] = b1;
    __syncthreads();

    for (int kt = 1; kt <= nk; ++kt) {
        if (kt < nk) {
            const float* Ap = Aptr + kt * 16;
            a0 = *(const float4*)(Ap);
            a1 = *(const float4*)(Ap + AstepRow);
            const float* Bp = Bptr + (long long)kt * 16 * N;
            b0 = *(const float4*)(Bp);
            b1 = *(const float4*)(Bp + BstepRow);
        }
#pragma unroll
        for (int k = 0; k < 16; ++k) {
            const float4 av0 = *(const float4*)&As[buf][k][ty * 8];
            const float4 av1 = *(const float4*)&As[buf][k][ty * 8 + 4];
            const ulonglong2 bv0 = *(const ulonglong2*)&Bs[buf][k][tx * 8];
            const ulonglong2 bv1 = *(const ulonglong2*)&Bs[buf][k][tx * 8 + 4];
            const unsigned long long bb0 = bv0.x, bb1 = bv0.y;
            const unsigned long long bb2 = bv1.x, bb3 = bv1.y;
            const float aval[8] = {av0.x, av0.y, av0.z, av0.w,
                                   av1.x, av1.y, av1.z, av1.w};
#pragma unroll
            for (int i = 0; i < 8; ++i) {
                const unsigned long long ap = pack2(aval[i]);
                acc[i][0] = fma2(ap, bb0, acc[i][0]);
                acc[i][1] = fma2(ap, bb1, acc[i][1]);
                acc[i][2] = fma2(ap, bb2, acc[i][2]);
                acc[i][3] = fma2(ap, bb3, acc[i][3]);
            }
        }
        if (kt < nk) {
            const int nb = buf ^ 1;
            As[nb][ac + 0][arow] = a0.x; As[nb][ac + 1][arow] = a0.y;
            As[nb][ac + 2][arow] = a0.z; As[nb][ac + 3][arow] = a0.w;
            As[nb][ac + 0][arow + 64] = a1.x; As[nb][ac + 1][arow + 64] = a1.y;
            As[nb][ac + 2][arow + 64] = a1.z; As[nb][ac + 3][arow + 64] = a1.w;
            *(float4*)&Bs[nb][brow][bc]     = b0;
            *(float4*)&Bs[nb][brow + 8][bc] = b1;
        }
        __syncthreads();
        buf ^= 1;
    }

    // epilogue
    const int col0 = Bcol0 + tx * 8;
    float bvv[8];
#pragma unroll
    for (int j = 0; j < 8; ++j) bvv[j] = __ldg(&bias[col0 + j]);

#pragma unroll
    for (int i = 0; i < 8; ++i) {
        const long long row = Arow0 + ty * 8 + i;
        float o[8];
#pragma unroll
        for (int j4 = 0; j4 < 4; ++j4) {
            float2 p = unpack2(acc[i][j4]);
            o[2 * j4]     = p.x;
            o[2 * j4 + 1] = p.y;
        }
#pragma unroll
        for (int j = 0; j < 8; ++j) {
            float v = o[j] + bvv[j];
            if (EPI == 0) v = v / (1.0f + expf(-v));   // silu
            o[j] = v;
        }
        float4 o0 = make_float4(o[0], o[1], o[2], o[3]);
        float4 o1 = make_float4(o[4], o[5], o[6], o[7]);
        *(float4*)(C + row * N + col0)     = o0;
        *(float4*)(C + row * N + col0 + 4) = o1;
    }
}

// ---------------------------------------------------------------------------
// Fold W into W2:  W2'[m, 64i+j] = sum_k W2[m, 64i+k] * W[j*64+k]
// One block per m-row. 256 threads, 4x4 register tile over (i,j).
// ---------------------------------------------------------------------------
__global__ __launch_bounds__(256)
void fold_w2(const float* __restrict__ W2, const float* __restrict__ W,
             float* __restrict__ W2p)
{
    __shared__ float Ws[64 * 65];
    __shared__ __align__(16) float Rm[4096];
    const int m = blockIdx.x;
    const int tid = threadIdx.x;

    for (int p = tid; p < 4096; p += 256)
        Ws[(p >> 6) * 65 + (p & 63)] = W[p];
    const float* src = W2 + (long long)m * 4096;
    for (int p = tid * 4; p < 4096; p += 1024)
        *(float4*)&Rm[p] = *(const float4*)&src[p];
    __syncthreads();

    const int tx = tid & 15, ty = tid >> 4;
    const int j0 = tx * 4, i0 = ty * 4;
    float acc[4][4] = {};
    for (int k = 0; k < 64; ++k) {
        float a[4], b[4];
#pragma unroll
        for (int u = 0; u < 4; ++u) a[u] = Rm[(i0 + u) * 64 + k];
#pragma unroll
        for (int u = 0; u < 4; ++u) b[u] = Ws[(j0 + u) * 65 + k];
#pragma unroll
        for (int u = 0; u < 4; ++u)
#pragma unroll
            for (int v = 0; v < 4; ++v) acc[u][v] = fmaf(a[u], b[v], acc[u][v]);
    }
    float* dst = W2p + (long long)m * 4096;
#pragma unroll
    for (int u = 0; u < 4; ++u) {
        float4 o = make_float4(acc[u][0], acc[u][1], acc[u][2], acc[u][3]);
        *(float4*)&dst[(i0 + u) * 64 + j0] = o;
    }
}

// b2'[64i+j] = sum_k b2[64i+k] * W[j*64+k]
__global__ void fold_b2(const float* __restrict__ b2,
                        const float* __restrict__ W,
                        float* __restrict__ b2p)
{
    const int p = blockIdx.x * 256 + threadIdx.x;   // 0..4095
    const int i = p >> 6, j = p & 63;
    float s = 0.0f;
    for (int k = 0; k < 64; ++k)
        s = fmaf(__ldg(&b2[i * 64 + k]), __ldg(&W[j * 64 + k]), s);
    b2p[p] = s;
}

// ---------------------------------------------------------------------------
// Per-sample: out_b = Ft_b @ Xp_b @ Ft_b^T,  Xp = [[x,0],[0,I16]].
// F buffer (= d_out) is read into smem, then overwritten with the result.
// ---------------------------------------------------------------------------
__global__ __launch_bounds__(256)
void spd_out(const float* __restrict__ X,   // [B,48,48]
             float* __restrict__ F)         // in: Ft rows; out: result
{
    __shared__ float Fs[64 * 65];   // Ft, padded stride 65 (col reads -> 2-way)
    __shared__ float Xs[48 * 49];
    __shared__ float Gs[64 * 64];   // G = Ft @ Xp

    const int b = blockIdx.x;
    const int tid = threadIdx.x;

    const float* Fg = F + (long long)b * 4096;
    for (int p = tid; p < 4096; p += 256)
        Fs[(p >> 6) * 65 + (p & 63)] = Fg[p];
    const float* Xg = X + (long long)b * 2304;
    for (int p = tid; p < 2304; p += 256)
        Xs[(p / 48) * 49 + (p % 48)] = Xg[p];
    __syncthreads();

    const int tx = tid & 15, ty = tid >> 4;
    const int i0 = ty * 4, k0 = tx * 4;

    // G[i,k] = sum_{j<48} Ft[i,j] x[j,k]   (k<48);   G[i,k] = Ft[i,k]  (k>=48)
    float g[4][4] = {};
    if (tx < 12) {
        for (int j = 0; j < 48; ++j) {
            float a[4], xb[4];
#pragma unroll
            for (int u = 0; u < 4; ++u) a[u]  = Fs[(i0 + u) * 65 + j];
#pragma unroll
            for (int u = 0; u < 4; ++u) xb[u] = Xs[j * 49 + k0 + u];
#pragma unroll
            for (int u = 0; u < 4; ++u)
#pragma unroll
                for (int v = 0; v < 4; ++v) g[u][v] = fmaf(a[u], xb[v], g[u][v]);
        }
    } else {
#pragma unroll
        for (int u = 0; u < 4; ++u)
#pragma unroll
            for (int v = 0; v < 4; ++v) g[u][v] = Fs[(i0 + u) * 65 + k0 + v];
    }
#pragma unroll
    for (int u = 0; u < 4; ++u)
#pragma unroll
        for (int v = 0; v < 4; ++v) Gs[(i0 + u) * 64 + k0 + v] = g[u][v];
    __syncthreads();

    // out[i,l] = sum_k G[i,k] * Ft[l,k]
    const int l0 = tx * 4;
    float acc[4][4] = {};
    for (int k = 0; k < 64; ++k) {
        float a[4], bb[4];
#pragma unroll
        for (int u = 0; u < 4; ++u) a[u]  = Gs[(i0 + u) * 64 + k];
#pragma unroll
        for (int u = 0; u < 4; ++u) bb[u] = Fs[(l0 + u) * 65 + k];
#pragma unroll
        for (int u = 0; u < 4; ++u)
#pragma unroll
            for (int v = 0; v < 4; ++v) acc[u][v] = fmaf(a[u], bb[v], acc[u][v]);
    }

    float* Og = F + (long long)b * 4096;
#pragma unroll
    for (int u = 0; u < 4; ++u) {
        float4 o = make_float4(acc[u][0], acc[u][1], acc[u][2], acc[u][3]);
        *(float4*)&Og[(i0 + u) * 64 + l0] = o;
    }
}

// ---------------------------------------------------------------------------
extern "C" void kernel_launch(void* const* d_in, const int* in_sizes, int n_in,
                              void* d_out, int out_size)
{
    const float* x  = (const float*)d_in[0];  // [4096,48,48]
    // d_in[1] = t  (unused by reference)
    const float* Y  = (const float*)d_in[2];  // [4096,64]
    const float* W  = (const float*)d_in[3];  // [64,64]
    const float* W1 = (const float*)d_in[4];  // [64,4096]
    const float* b1 = (const float*)d_in[5];  // [4096]
    const float* W2 = (const float*)d_in[6];  // [4096,4096]
    const float* b2 = (const float*)d_in[7];  // [4096]
    float* out = (float*)d_out;               // [4096,64,64]

    float *hbuf, *w2p, *b2p;
    cudaGetSymbolAddress((void**)&hbuf, g_h);
    cudaGetSymbolAddress((void**)&w2p,  g_W2p);
    cudaGetSymbolAddress((void**)&b2p,  g_b2p);

    // 1) fold W into W2 / b2
    fold_w2<<<4096, 256>>>(W2, W, w2p);
    fold_b2<<<16, 256>>>(b2, W, b2p);

    // 2) h = silu(Y @ W1 + b1)        [4096,4096]
    gemm128<0><<<dim3(32, 32), 256>>>(Y, W1, b1, hbuf, 64, 4096);

    // 3) Ft = h @ W2' + b2'           [4096,4096]  (written into d_out)
    gemm128<1><<<dim3(32, 32), 256>>>(hbuf, w2p, b2p, out, 4096, 4096);

    // 4) out_b = Ft_b @ Xp_b @ Ft_b^T  (in-place over d_out)
    spd_out<<<4096, 256>>>(x, out);
}

// round 8
// speedup vs baseline: 1.7186x; 1.7186x over previous
#include <cuda_runtime.h>
#include <cuda_bf16.h>
#include <math.h>
#include <stdint.h>

// ---------------------------------------------------------------------------
// SPDTransform, base-target tensor path (mma.sync bf16; tcgen05 is rejected by
// this toolchain's ptxas target sm_103):
//   W2t'[n,k] = (W2 @ blockdiag(W))^T folded  -> bf16 hi/lo  [N=4096,K=4096]
//   h  = silu(Y@W1+b1)                        -> bf16 hi/lo  [M=4096,K=4096]
//   Ft = h @ W2'^T + b2'  via 3-product bf16-split mma.sync -> d_out fp32
//   out_b = Ft_b @ Xp_b @ Ft_b^T   (per-sample, Xp = [[x,0],[0,I16]])
// ---------------------------------------------------------------------------

__device__ __nv_bfloat16 g_Ahi[16777216];
__device__ __nv_bfloat16 g_Alo[16777216];
__device__ __nv_bfloat16 g_Bhi[16777216];
__device__ __nv_bfloat16 g_Blo[16777216];
__device__ float         g_b2p[4096];

__device__ __forceinline__ uint32_t smem_u32(const void* p) {
    uint32_t a;
    asm("{ .reg .u64 t; cvta.to.shared.u64 t, %1; cvt.u32.u64 %0, t; }"
        : "=r"(a) : "l"(p));
    return a;
}
__device__ __forceinline__ void cpa16(uint32_t d, const void* s) {
    asm volatile("cp.async.cg.shared.global [%0], [%1], 16;" :: "r"(d), "l"(s)
                 : "memory");
}
__device__ __forceinline__ void ldmx4(uint32_t* r, uint32_t a) {
    asm volatile("ldmatrix.sync.aligned.m8n8.x4.shared.b16 {%0,%1,%2,%3}, [%4];"
                 : "=r"(r[0]), "=r"(r[1]), "=r"(r[2]), "=r"(r[3]) : "r"(a));
}
__device__ __forceinline__ void mma16816(float* c, const uint32_t* a,
                                         uint32_t b0, uint32_t b1) {
    asm volatile(
        "mma.sync.aligned.m16n8k16.row.col.f32.bf16.bf16.f32 "
        "{%0,%1,%2,%3}, {%4,%5,%6,%7}, {%8,%9}, {%0,%1,%2,%3};"
        : "+f"(c[0]), "+f"(c[1]), "+f"(c[2]), "+f"(c[3])
        : "r"(a[0]), "r"(a[1]), "r"(a[2]), "r"(a[3]), "r"(b0), "r"(b1));
}

// stage layout (bytes): Ahi 8K | Alo 8K | Bhi 16K | Blo 16K  = 48K
static constexpr int ST_ALO = 8192;
static constexpr int ST_BHI = 16384;
static constexpr int ST_BLO = 32768;
static constexpr int STAGE  = 49152;
static constexpr int STAGES = 3;
static constexpr int GTC_SMEM = STAGES * STAGE;   // 144 KB

// ---------------------------------------------------------------------------
// C[M=4096, N=4096] = A @ B^T (+bias), A[M,K],B[N,K] bf16 hi/lo, K=4096.
// 3-product split: AhBh + AlBh + AhBl, fp32 accum.
// Tile 128x256, BK=32, 256 thr, warp 64x64. grid (16 n, 32 m).
// 3-stage cp.async pipeline, single __syncthreads per k-chunk.
// ---------------------------------------------------------------------------
__global__ __launch_bounds__(256, 1)
void gemm_mma(const __nv_bfloat16* __restrict__ Ahi, const __nv_bfloat16* __restrict__ Alo,
              const __nv_bfloat16* __restrict__ Bhi, const __nv_bfloat16* __restrict__ Blo,
              const float* __restrict__ bias, float* __restrict__ C)
{
    extern __shared__ char dsm[];
    const uint32_t base = smem_u32(dsm);

    const int tid  = threadIdx.x;
    const int lane = tid & 31;
    const int wid  = tid >> 5;
    const int warp_m = wid >> 2;            // 0..1  -> 64 rows
    const int warp_n = wid & 3;             // 0..3  -> 64 cols
    const int m0 = blockIdx.y * 128;
    const int n0 = blockIdx.x * 256;

    // smem swizzle: row r (64B), logical 16B seg s -> phys seg s ^ ((r>>1)&3)
    auto load_stage = [&](int kt, int s) {
        const uint32_t sb = base + s * STAGE;
        const int kc = kt * 32;
#pragma unroll
        for (int it = 0; it < 2; ++it) {
            const int idx = tid + it * 256;          // 0..511
            const int r = idx >> 2, sg = idx & 3;
            const uint32_t d = (uint32_t)(r * 64 + ((sg ^ ((r >> 1) & 3)) << 4));
            const size_t go = (size_t)(m0 + r) * 4096 + kc + sg * 8;
            cpa16(sb + d,          Ahi + go);
            cpa16(sb + ST_ALO + d, Alo + go);
        }
#pragma unroll
        for (int it = 0; it < 4; ++it) {
            const int idx = tid + it * 256;          // 0..1023
            const int r = idx >> 2, sg = idx & 3;
            const uint32_t d = (uint32_t)(r * 64 + ((sg ^ ((r >> 1) & 3)) << 4));
            const size_t go = (size_t)(n0 + r) * 4096 + kc + sg * 8;
            cpa16(sb + ST_BHI + d, Bhi + go);
            cpa16(sb + ST_BLO + d, Blo + go);
        }
        asm volatile("cp.async.commit_group;" ::: "memory");
    };

    // prologue: stages 0,1 in flight
    load_stage(0, 0);
    load_stage(1, 1);

    float acc[4][8][4];
#pragma unroll
    for (int i = 0; i < 4; ++i)
#pragma unroll
        for (int j = 0; j < 8; ++j)
#pragma unroll
            for (int v = 0; v < 4; ++v) acc[i][j][v] = 0.0f;

    const int rA0 = warp_m * 64 + (lane & 15);
    const int rB0 = warp_n * 64 + (lane & 15);
    const int shi = lane >> 4;                    // 16B seg within k16
    const int swz = ((lane & 15) >> 1) & 3;       // row-derived xor

    int sidx = 0;                                 // stage of kt (mod 3)
#pragma unroll 1
    for (int kt = 0; kt < 128; ++kt) {
        asm volatile("cp.async.wait_group 1;" ::: "memory");
        __syncthreads();   // stage kt visible; all warps done with stage kt-1

        if (kt + 2 < 128) {
            int ps = sidx + 2; if (ps >= 3) ps -= 3;
            load_stage(kt + 2, ps);               // overwrites stage of kt-1
        }

        const uint32_t sb = base + sidx * STAGE;
#pragma unroll
        for (int ks = 0; ks < 2; ++ks) {
            const int slog = ks * 2 + shi;
            const uint32_t segoff = (uint32_t)((slog ^ swz) << 4);
            uint32_t ah[4][4], al[4][4], bb[4][4];
#pragma unroll
            for (int mt = 0; mt < 4; ++mt) {
                const uint32_t off = (uint32_t)((rA0 + mt * 16) * 64) + segoff;
                ldmx4(ah[mt], sb + off);
                ldmx4(al[mt], sb + ST_ALO + off);
            }
#pragma unroll
            for (int bt = 0; bt < 4; ++bt) {
                const uint32_t off = (uint32_t)((rB0 + bt * 16) * 64) + segoff;
                ldmx4(bb[bt], sb + ST_BHI + off);
            }
            // products 1+2: Ah*Bh, Al*Bh
#pragma unroll
            for (int mt = 0; mt < 4; ++mt)
#pragma unroll
                for (int nt = 0; nt < 8; ++nt) {
                    const uint32_t b0 = bb[nt >> 1][nt & 1];
                    const uint32_t b1 = bb[nt >> 1][(nt & 1) + 2];
                    mma16816(acc[mt][nt], ah[mt], b0, b1);
                    mma16816(acc[mt][nt], al[mt], b0, b1);
                }
            // product 3: Ah*Bl (reuse bb regs)
#pragma unroll
            for (int bt = 0; bt < 4; ++bt) {
                const uint32_t off = (uint32_t)((rB0 + bt * 16) * 64) + segoff;
                ldmx4(bb[bt], sb + ST_BLO + off);
            }
#pragma unroll
            for (int mt = 0; mt < 4; ++mt)
#pragma unroll
                for (int nt = 0; nt < 8; ++nt) {
                    const uint32_t b0 = bb[nt >> 1][nt & 1];
                    const uint32_t b1 = bb[nt >> 1][(nt & 1) + 2];
                    mma16816(acc[mt][nt], ah[mt], b0, b1);
                }
        }
        ++sidx; if (sidx >= 3) sidx = 0;
    }

    // epilogue: c frag lane l -> rows l/4, l/4+8; cols 2*(l&3)+{0,1}
#pragma unroll
    for (int mt = 0; mt < 4; ++mt)
#pragma unroll
        for (int nt = 0; nt < 8; ++nt) {
            const float* c = acc[mt][nt];
            const int row = m0 + warp_m * 64 + mt * 16 + (lane >> 2);
            const int col = n0 + warp_n * 64 + nt * 8 + 2 * (lane & 3);
            const float bv0 = __ldg(&bias[col]);
            const float bv1 = __ldg(&bias[col + 1]);
            float2 o0 = make_float2(c[0] + bv0, c[1] + bv1);
            float2 o1 = make_float2(c[2] + bv0, c[3] + bv1);
            *(float2*)(C + (size_t)row * 4096 + col)       = o0;
            *(float2*)(C + (size_t)(row + 8) * 4096 + col) = o1;
        }
}

// ---------------------------------------------------------------------------
// h = silu(Y @ W1 + b1), emitted as bf16 hi/lo. FFMA kernel (K=64, tiny).
// ---------------------------------------------------------------------------
__global__ __launch_bounds__(256, 2)
void gemm_h(const float* __restrict__ A, const float* __restrict__ B,
            const float* __restrict__ bias,
            __nv_bfloat16* __restrict__ Chi, __nv_bfloat16* __restrict__ Clo,
            int K, int N)
{
    __shared__ __align__(16) float As[2][16][132];
    __shared__ __align__(16) float Bs[2][16][128];

    const int tid = threadIdx.x;
    const int tx = tid & 15, ty = tid >> 4;
    const long long Arow0 = (long long)blockIdx.y * 128;
    const int Bcol0 = blockIdx.x * 128;

    const int arow = tid >> 2, ac = (tid & 3) << 2;
    const int brow = tid >> 5, bc = (tid & 31) << 2;

    const float* Aptr = A + (Arow0 + arow) * (long long)K + ac;
    const float* Bptr = B + (long long)brow * N + Bcol0 + bc;
    const long long AstepRow = 64LL * K;
    const long long BstepRow = 8LL * N;

    float acc[8][8] = {};
    const int nk = K >> 4;

    float4 a0 = *(const float4*)(Aptr);
    float4 a1 = *(const float4*)(Aptr + AstepRow);
    float4 b0 = *(const float4*)(Bptr);
    float4 b1 = *(const float4*)(Bptr + BstepRow);

    int buf = 0;
    As[0][ac + 0][arow] = a0.x; As[0][ac + 1][arow] = a0.y;
    As[0][ac + 2][arow] = a0.z; As[0][ac + 3][arow] = a0.w;
    As[0][ac + 0][arow + 64] = a1.x; As[0][ac + 1][arow + 64] = a1.y;
    As[0][ac + 2][arow + 64] = a1.z; As[0][ac + 3][arow + 64] = a1.w;
    *(float4*)&Bs[0][brow][bc]     = b0;
    *(float4*)&Bs[0][brow + 8][bc] = b1;
    __syncthreads();

    for (int kt = 1; kt <= nk; ++kt) {
        if (kt < nk) {
            const float* Ap = Aptr + kt * 16;
            a0 = *(const float4*)(Ap);
            a1 = *(const float4*)(Ap + AstepRow);
            const float* Bp = Bptr + (long long)kt * 16 * N;
            b0 = *(const float4*)(Bp);
            b1 = *(const float4*)(Bp + BstepRow);
        }
#pragma unroll
        for (int k = 0; k < 16; ++k) {
            float av[8], bv[8];
            *(float4*)&av[0] = *(const float4*)&As[buf][k][ty * 8];
            *(float4*)&av[4] = *(const float4*)&As[buf][k][ty * 8 + 4];
            *(float4*)&bv[0] = *(const float4*)&Bs[buf][k][tx * 8];
            *(float4*)&bv[4] = *(const float4*)&Bs[buf][k][tx * 8 + 4];
#pragma unroll
            for (int i = 0; i < 8; ++i)
#pragma unroll
                for (int j = 0; j < 8; ++j)
                    acc[i][j] = fmaf(av[i], bv[j], acc[i][j]);
        }
        if (kt < nk) {
            const int nb = buf ^ 1;
            As[nb][ac + 0][arow] = a0.x; As[nb][ac + 1][arow] = a0.y;
            As[nb][ac + 2][arow] = a0.z; As[nb][ac + 3][arow] = a0.w;
            As[nb][ac + 0][arow + 64] = a1.x; As[nb][ac + 1][arow + 64] = a1.y;
            As[nb][ac + 2][arow + 64] = a1.z; As[nb][ac + 3][arow + 64] = a1.w;
            *(float4*)&Bs[nb][brow][bc]     = b0;
            *(float4*)&Bs[nb][brow + 8][bc] = b1;
        }
        __syncthreads();
        buf ^= 1;
    }

    const int col0 = Bcol0 + tx * 8;
#pragma unroll
    for (int i = 0; i < 8; ++i) {
        const long long row = Arow0 + ty * 8 + i;
        union { __nv_bfloat16 h[8]; uint4 u; } ph, pl;
#pragma unroll
        for (int j = 0; j < 8; ++j) {
            float v = acc[i][j] + __ldg(&bias[col0 + j]);
            v = v / (1.0f + expf(-v));                 // silu
            __nv_bfloat16 hi = __float2bfloat16(v);
            ph.h[j] = hi;
            pl.h[j] = __float2bfloat16(v - __bfloat162float(hi));
        }
        *(uint4*)&Chi[row * N + col0] = ph.u;
        *(uint4*)&Clo[row * N + col0] = pl.u;
    }
}

// ---------------------------------------------------------------------------
// Fold + transpose: B[n=64i+j, k=m] = sum_t W2[m,64i+t] * W[j*64+t], bf16 hi/lo
// ---------------------------------------------------------------------------
__global__ __launch_bounds__(256)
void fold_w2t(const float* __restrict__ W2, const float* __restrict__ W,
              __nv_bfloat16* __restrict__ Bhi, __nv_bfloat16* __restrict__ Blo)
{
    __shared__ float W2s[64][65];
    __shared__ float Ws[64][64];
    const int i = blockIdx.x;
    const int m0 = blockIdx.y * 64;
    const int tid = threadIdx.x;

    for (int p = tid; p < 4096; p += 256) {
        const int mm = p >> 6, k = p & 63;
        W2s[mm][k] = W2[(size_t)(m0 + mm) * 4096 + i * 64 + k];
    }
    for (int p = tid; p < 4096; p += 256) Ws[p >> 6][p & 63] = W[p];
    __syncthreads();

    const int mm = tid & 63, jg = tid >> 6;
#pragma unroll 1
    for (int jj = 0; jj < 16; ++jj) {
        const int j = jg * 16 + jj;
        float acc = 0.0f;
#pragma unroll
        for (int k = 0; k < 64; ++k) acc = fmaf(W2s[mm][k], Ws[j][k], acc);
        const size_t o = (size_t)(i * 64 + j) * 4096 + m0 + mm;
        __nv_bfloat16 hi = __float2bfloat16(acc);
        Bhi[o] = hi;
        Blo[o] = __float2bfloat16(acc - __bfloat162float(hi));
    }
}

// b2'[64i+j] = sum_k b2[64i+k] * W[j*64+k]
__global__ void fold_b2(const float* __restrict__ b2,
                        const float* __restrict__ W,
                        float* __restrict__ b2p)
{
    const int p = blockIdx.x * 256 + threadIdx.x;
    const int i = p >> 6, j = p & 63;
    float s = 0.0f;
    for (int k = 0; k < 64; ++k)
        s = fmaf(__ldg(&b2[i * 64 + k]), __ldg(&W[j * 64 + k]), s);
    b2p[p] = s;
}

// ---------------------------------------------------------------------------
// Per-sample: out_b = Ft_b @ Xp_b @ Ft_b^T,  Xp = [[x,0],[0,I16]]  (in-place)
// ---------------------------------------------------------------------------
__global__ __launch_bounds__(256)
void spd_out(const float* __restrict__ X, float* __restrict__ F)
{
    __shared__ float Fs[64 * 65];
    __shared__ float Xs[48 * 49];
    __shared__ float Gs[64 * 64];

    const int b = blockIdx.x;
    const int tid = threadIdx.x;

    const float* Fg = F + (long long)b * 4096;
    for (int p = tid; p < 4096; p += 256)
        Fs[(p >> 6) * 65 + (p & 63)] = Fg[p];
    const float* Xg = X + (long long)b * 2304;
    for (int p = tid; p < 2304; p += 256)
        Xs[(p / 48) * 49 + (p % 48)] = Xg[p];
    __syncthreads();

    const int tx = tid & 15, ty = tid >> 4;
    const int i0 = ty * 4, k0 = tx * 4;

    float g[4][4] = {};
    if (tx < 12) {
        for (int j = 0; j < 48; ++j) {
            float a[4], xb[4];
#pragma unroll
            for (int u = 0; u < 4; ++u) a[u]  = Fs[(i0 + u) * 65 + j];
#pragma unroll
            for (int u = 0; u < 4; ++u) xb[u] = Xs[j * 49 + k0 + u];
#pragma unroll
            for (int u = 0; u < 4; ++u)
#pragma unroll
                for (int v = 0; v < 4; ++v) g[u][v] = fmaf(a[u], xb[v], g[u][v]);
        }
    } else {
#pragma unroll
        for (int u = 0; u < 4; ++u)
#pragma unroll
            for (int v = 0; v < 4; ++v) g[u][v] = Fs[(i0 + u) * 65 + k0 + v];
    }
#pragma unroll
    for (int u = 0; u < 4; ++u)
#pragma unroll
        for (int v = 0; v < 4; ++v) Gs[(i0 + u) * 64 + k0 + v] = g[u][v];
    __syncthreads();

    const int l0 = tx * 4;
    float acc[4][4] = {};
    for (int k = 0; k < 64; ++k) {
        float a[4], bb[4];
#pragma unroll
        for (int u = 0; u < 4; ++u) a[u]  = Gs[(i0 + u) * 64 + k];
#pragma unroll
        for (int u = 0; u < 4; ++u) bb[u] = Fs[(l0 + u) * 65 + k];
#pragma unroll
        for (int u = 0; u < 4; ++u)
#pragma unroll
            for (int v = 0; v < 4; ++v) acc[u][v] = fmaf(a[u], bb[v], acc[u][v]);
    }

    float* Og = F + (long long)b * 4096;
#pragma unroll
    for (int u = 0; u < 4; ++u) {
        float4 o = make_float4(acc[u][0], acc[u][1], acc[u][2], acc[u][3]);
        *(float4*)&Og[(i0 + u) * 64 + l0] = o;
    }
}

// ---------------------------------------------------------------------------
extern "C" void kernel_launch(void* const* d_in, const int* in_sizes, int n_in,
                              void* d_out, int out_size)
{
    const float* x  = (const float*)d_in[0];  // [4096,48,48]
    const float* Y  = (const float*)d_in[2];  // [4096,64]
    const float* W  = (const float*)d_in[3];  // [64,64]
    const float* W1 = (const float*)d_in[4];  // [64,4096]
    const float* b1 = (const float*)d_in[5];  // [4096]
    const float* W2 = (const float*)d_in[6];  // [4096,4096]
    const float* b2 = (const float*)d_in[7];  // [4096]
    float* out = (float*)d_out;               // [4096,64,64]

    __nv_bfloat16 *ahi, *alo, *bhi, *blo;
    float* b2p;
    cudaGetSymbolAddress((void**)&ahi, g_Ahi);
    cudaGetSymbolAddress((void**)&alo, g_Alo);
    cudaGetSymbolAddress((void**)&bhi, g_Bhi);
    cudaGetSymbolAddress((void**)&blo, g_Blo);
    cudaGetSymbolAddress((void**)&b2p, g_b2p);

    cudaFuncSetAttribute(gemm_mma, cudaFuncAttributeMaxDynamicSharedMemorySize,
                         GTC_SMEM);

    fold_w2t<<<dim3(64, 64), 256>>>(W2, W, bhi, blo);
    fold_b2<<<16, 256>>>(b2, W, b2p);
    gemm_h<<<dim3(32, 32), 256>>>(Y, W1, b1, ahi, alo, 64, 4096);
    gemm_mma<<<dim3(16, 32), 256, GTC_SMEM>>>(ahi, alo, bhi, blo, b2p, out);
    spd_out<<<4096, 256>>>(x, out);
}

// round 9
// speedup vs baseline: 1.8241x; 1.0614x over previous
#include <cuda_runtime.h>
#include <cuda_bf16.h>
#include <math.h>
#include <stdint.h>

// ---------------------------------------------------------------------------
// SPDTransform, base-target tensor path (mma.sync bf16):
//   W2t'[n,k] = (W2 @ blockdiag(W))^T folded  -> bf16 hi/lo  [N=4096,K=4096]
//   h  = silu(Y@W1+b1)                        -> bf16 hi/lo  [M=4096,K=4096]
//   Ft = h @ W2'^T + b2'  via 3-product bf16-split mma.sync -> d_out fp32
//   out_b = Ft_b @ Xp_b @ Ft_b^T   (per-sample, Xp = [[x,0],[0,I16]])
// ---------------------------------------------------------------------------

__device__ __nv_bfloat16 g_Ahi[16777216];
__device__ __nv_bfloat16 g_Alo[16777216];
__device__ __nv_bfloat16 g_Bhi[16777216];
__device__ __nv_bfloat16 g_Blo[16777216];
__device__ float         g_b2p[4096];

__device__ __forceinline__ uint32_t smem_u32(const void* p) {
    uint32_t a;
    asm("{ .reg .u64 t; cvta.to.shared.u64 t, %1; cvt.u32.u64 %0, t; }"
        : "=r"(a) : "l"(p));
    return a;
}
__device__ __forceinline__ void cpa16(uint32_t d, const void* s) {
    asm volatile("cp.async.cg.shared.global [%0], [%1], 16;" :: "r"(d), "l"(s)
                 : "memory");
}
__device__ __forceinline__ void ldmx4(uint32_t* r, uint32_t a) {
    asm volatile("ldmatrix.sync.aligned.m8n8.x4.shared.b16 {%0,%1,%2,%3}, [%4];"
                 : "=r"(r[0]), "=r"(r[1]), "=r"(r[2]), "=r"(r[3]) : "r"(a));
}
__device__ __forceinline__ void mma16816(float* c, const uint32_t* a,
                                         uint32_t b0, uint32_t b1) {
    asm volatile(
        "mma.sync.aligned.m16n8k16.row.col.f32.bf16.bf16.f32 "
        "{%0,%1,%2,%3}, {%4,%5,%6,%7}, {%8,%9}, {%0,%1,%2,%3};"
        : "+f"(c[0]), "+f"(c[1]), "+f"(c[2]), "+f"(c[3])
        : "r"(a[0]), "r"(a[1]), "r"(a[2]), "r"(a[3]), "r"(b0), "r"(b1));
}

// BK=64: row = 64 bf16 = 128 bytes.
// stage layout (bytes): Ahi 16K | Alo 16K | Bhi 32K | Blo 32K = 96K
static constexpr int ST_ALO = 16384;
static constexpr int ST_BHI = 32768;
static constexpr int ST_BLO = 65536;
static constexpr int STAGE  = 98304;
static constexpr int STAGES = 2;
static constexpr int GTC_SMEM = STAGES * STAGE;   // 192 KB

// ---------------------------------------------------------------------------
// C[M=4096, N=4096] = A @ B^T (+bias), A[M,K],B[N,K] bf16 hi/lo, K=4096.
// 3-product split: AhBh + AlBh + AhBl, fp32 accum.
// Tile 128x256, BK=64, 256 thr, warp 64x64. grid (16 n, 32 m).
// 2-stage cp.async double buffer; all 16 LDSM per k16 issued up front.
// ---------------------------------------------------------------------------
__global__ __launch_bounds__(256, 1)
void gemm_mma(const __nv_bfloat16* __restrict__ Ahi, const __nv_bfloat16* __restrict__ Alo,
              const __nv_bfloat16* __restrict__ Bhi, const __nv_bfloat16* __restrict__ Blo,
              const float* __restrict__ bias, float* __restrict__ C)
{
    extern __shared__ char dsm[];
    const uint32_t base = smem_u32(dsm);

    const int tid  = threadIdx.x;
    const int lane = tid & 31;
    const int wid  = tid >> 5;
    const int warp_m = wid >> 2;            // 0..1  -> 64 rows
    const int warp_n = wid & 3;             // 0..3  -> 64 cols
    const int m0 = blockIdx.y * 128;
    const int n0 = blockIdx.x * 256;

    // swizzle: row r (128B), logical 16B seg s (0..7) -> phys seg s ^ (r&7)
    auto load_stage = [&](int kt, int s) {
        const uint32_t sb = base + s * STAGE;
        const int kc = kt * 64;
#pragma unroll
        for (int it = 0; it < 4; ++it) {
            const int idx = tid + it * 256;          // 0..1023
            const int r = idx >> 3, sg = idx & 7;
            const uint32_t d = (uint32_t)(r * 128 + ((sg ^ (r & 7)) << 4));
            const size_t go = (size_t)(m0 + r) * 4096 + kc + sg * 8;
            cpa16(sb + d,          Ahi + go);
            cpa16(sb + ST_ALO + d, Alo + go);
        }
#pragma unroll
        for (int it = 0; it < 8; ++it) {
            const int idx = tid + it * 256;          // 0..2047
            const int r = idx >> 3, sg = idx & 7;
            const uint32_t d = (uint32_t)(r * 128 + ((sg ^ (r & 7)) << 4));
            const size_t go = (size_t)(n0 + r) * 4096 + kc + sg * 8;
            cpa16(sb + ST_BHI + d, Bhi + go);
            cpa16(sb + ST_BLO + d, Blo + go);
        }
        asm volatile("cp.async.commit_group;" ::: "memory");
    };

    load_stage(0, 0);

    float acc[4][8][4];
#pragma unroll
    for (int i = 0; i < 4; ++i)
#pragma unroll
        for (int j = 0; j < 8; ++j)
#pragma unroll
            for (int v = 0; v < 4; ++v) acc[i][j][v] = 0.0f;

    const int rA0 = warp_m * 64 + (lane & 15);
    const int rB0 = warp_n * 64 + (lane & 15);
    const int shi = lane >> 4;                    // 16B seg within k16
    const int swz = (lane & 15) & 7;              // row-derived xor

#pragma unroll 1
    for (int kt = 0; kt < 64; ++kt) {
        asm volatile("cp.async.wait_group 0;" ::: "memory");
        __syncthreads();   // stage kt visible; all warps done with stage kt-1

        if (kt + 1 < 64) load_stage(kt + 1, (kt + 1) & 1);

        const uint32_t sb = base + (kt & 1) * STAGE;
#pragma unroll
        for (int ks = 0; ks < 4; ++ks) {
            const int slog = ks * 2 + shi;
            const uint32_t segoff = (uint32_t)(((slog ^ swz) & 7) << 4);
            uint32_t ah[4][4], al[4][4], bh[4][4], bl[4][4];
#pragma unroll
            for (int mt = 0; mt < 4; ++mt) {
                const uint32_t off = (uint32_t)((rA0 + mt * 16) * 128) + segoff;
                ldmx4(ah[mt], sb + off);
                ldmx4(al[mt], sb + ST_ALO + off);
            }
#pragma unroll
            for (int bt = 0; bt < 4; ++bt) {
                const uint32_t off = (uint32_t)((rB0 + bt * 16) * 128) + segoff;
                ldmx4(bh[bt], sb + ST_BHI + off);
                ldmx4(bl[bt], sb + ST_BLO + off);
            }
#pragma unroll
            for (int mt = 0; mt < 4; ++mt)
#pragma unroll
                for (int nt = 0; nt < 8; ++nt) {
                    const uint32_t h0 = bh[nt >> 1][nt & 1];
                    const uint32_t h1 = bh[nt >> 1][(nt & 1) + 2];
                    mma16816(acc[mt][nt], ah[mt], h0, h1);
                    mma16816(acc[mt][nt], al[mt], h0, h1);
                    mma16816(acc[mt][nt], ah[mt],
                             bl[nt >> 1][nt & 1], bl[nt >> 1][(nt & 1) + 2]);
                }
        }
        __syncthreads();   // keep slow warps off next stage overwrite
    }

    // epilogue: c frag lane l -> rows l/4, l/4+8; cols 2*(l&3)+{0,1}
#pragma unroll
    for (int mt = 0; mt < 4; ++mt)
#pragma unroll
        for (int nt = 0; nt < 8; ++nt) {
            const float* c = acc[mt][nt];
            const int row = m0 + warp_m * 64 + mt * 16 + (lane >> 2);
            const int col = n0 + warp_n * 64 + nt * 8 + 2 * (lane & 3);
            const float bv0 = __ldg(&bias[col]);
            const float bv1 = __ldg(&bias[col + 1]);
            float2 o0 = make_float2(c[0] + bv0, c[1] + bv1);
            float2 o1 = make_float2(c[2] + bv0, c[3] + bv1);
            *(float2*)(C + (size_t)row * 4096 + col)       = o0;
            *(float2*)(C + (size_t)(row + 8) * 4096 + col) = o1;
        }
}

// ---------------------------------------------------------------------------
// h = silu(Y @ W1 + b1), emitted as bf16 hi/lo. FFMA kernel (K=64, tiny).
// ---------------------------------------------------------------------------
__global__ __launch_bounds__(256, 2)
void gemm_h(const float* __restrict__ A, const float* __restrict__ B,
            const float* __restrict__ bias,
            __nv_bfloat16* __restrict__ Chi, __nv_bfloat16* __restrict__ Clo,
            int K, int N)
{
    __shared__ __align__(16) float As[2][16][132];
    __shared__ __align__(16) float Bs[2][16][128];

    const int tid = threadIdx.x;
    const int tx = tid & 15, ty = tid >> 4;
    const long long Arow0 = (long long)blockIdx.y * 128;
    const int Bcol0 = blockIdx.x * 128;

    const int arow = tid >> 2, ac = (tid & 3) << 2;
    const int brow = tid >> 5, bc = (tid & 31) << 2;

    const float* Aptr = A + (Arow0 + arow) * (long long)K + ac;
    const float* Bptr = B + (long long)brow * N + Bcol0 + bc;
    const long long AstepRow = 64LL * K;
    const long long BstepRow = 8LL * N;

    float acc[8][8] = {};
    const int nk = K >> 4;

    float4 a0 = *(const float4*)(Aptr);
    float4 a1 = *(const float4*)(Aptr + AstepRow);
    float4 b0 = *(const float4*)(Bptr);
    float4 b1 = *(const float4*)(Bptr + BstepRow);

    int buf = 0;
    As[0][ac + 0][arow] = a0.x; As[0][ac + 1][arow] = a0.y;
    As[0][ac + 2][arow] = a0.z; As[0][ac + 3][arow] = a0.w;
    As[0][ac + 0][arow + 64] = a1.x; As[0][ac + 1][arow + 64] = a1.y;
    As[0][ac + 2][arow + 64] = a1.z; As[0][ac + 3][arow + 64] = a1.w;
    *(float4*)&Bs[0][brow][bc]     = b0;
    *(float4*)&Bs[0][brow + 8][bc] = b1;
    __syncthreads();

    for (int kt = 1; kt <= nk; ++kt) {
        if (kt < nk) {
            const float* Ap = Aptr + kt * 16;
            a0 = *(const float4*)(Ap);
            a1 = *(const float4*)(Ap + AstepRow);
            const float* Bp = Bptr + (long long)kt * 16 * N;
            b0 = *(const float4*)(Bp);
            b1 = *(const float4*)(Bp + BstepRow);
        }
#pragma unroll
        for (int k = 0; k < 16; ++k) {
            float av[8], bv[8];
            *(float4*)&av[0] = *(const float4*)&As[buf][k][ty * 8];
            *(float4*)&av[4] = *(const float4*)&As[buf][k][ty * 8 + 4];
            *(float4*)&bv[0] = *(const float4*)&Bs[buf][k][tx * 8];
            *(float4*)&bv[4] = *(const float4*)&Bs[buf][k][tx * 8 + 4];
#pragma unroll
            for (int i = 0; i < 8; ++i)
#pragma unroll
                for (int j = 0; j < 8; ++j)
                    acc[i][j] = fmaf(av[i], bv[j], acc[i][j]);
        }
        if (kt < nk) {
            const int nb = buf ^ 1;
            As[nb][ac + 0][arow] = a0.x; As[nb][ac + 1][arow] = a0.y;
            As[nb][ac + 2][arow] = a0.z; As[nb][ac + 3][arow] = a0.w;
            As[nb][ac + 0][arow + 64] = a1.x; As[nb][ac + 1][arow + 64] = a1.y;
            As[nb][ac + 2][arow + 64] = a1.z; As[nb][ac + 3][arow + 64] = a1.w;
            *(float4*)&Bs[nb][brow][bc]     = b0;
            *(float4*)&Bs[nb][brow + 8][bc] = b1;
        }
        __syncthreads();
        buf ^= 1;
    }

    const int col0 = Bcol0 + tx * 8;
#pragma unroll
    for (int i = 0; i < 8; ++i) {
        const long long row = Arow0 + ty * 8 + i;
        union { __nv_bfloat16 h[8]; uint4 u; } ph, pl;
#pragma unroll
        for (int j = 0; j < 8; ++j) {
            float v = acc[i][j] + __ldg(&bias[col0 + j]);
            v = v / (1.0f + expf(-v));                 // silu
            __nv_bfloat16 hi = __float2bfloat16(v);
            ph.h[j] = hi;
            pl.h[j] = __float2bfloat16(v - __bfloat162float(hi));
        }
        *(uint4*)&Chi[row * N + col0] = ph.u;
        *(uint4*)&Clo[row * N + col0] = pl.u;
    }
}

// ---------------------------------------------------------------------------
// Fold + transpose: B[n=64i+j, k=m] = sum_t W2[m,64i+t] * W[j*64+t], bf16 hi/lo
// ---------------------------------------------------------------------------
__global__ __launch_bounds__(256)
void fold_w2t(const float* __restrict__ W2, const float* __restrict__ W,
              __nv_bfloat16* __restrict__ Bhi, __nv_bfloat16* __restrict__ Blo)
{
    __shared__ float W2s[64][65];
    __shared__ float Ws[64][64];
    const int i = blockIdx.x;
    const int m0 = blockIdx.y * 64;
    const int tid = threadIdx.x;

    for (int p = tid; p < 4096; p += 256) {
        const int mm = p >> 6, k = p & 63;
        W2s[mm][k] = W2[(size_t)(m0 + mm) * 4096 + i * 64 + k];
    }
    for (int p = tid; p < 4096; p += 256) Ws[p >> 6][p & 63] = W[p];
    __syncthreads();

    const int mm = tid & 63, jg = tid >> 6;
#pragma unroll 1
    for (int jj = 0; jj < 16; ++jj) {
        const int j = jg * 16 + jj;
        float acc = 0.0f;
#pragma unroll
        for (int k = 0; k < 64; ++k) acc = fmaf(W2s[mm][k], Ws[j][k], acc);
        const size_t o = (size_t)(i * 64 + j) * 4096 + m0 + mm;
        __nv_bfloat16 hi = __float2bfloat16(acc);
        Bhi[o] = hi;
        Blo[o] = __float2bfloat16(acc - __bfloat162float(hi));
    }
}

// b2'[64i+j] = sum_k b2[64i+k] * W[j*64+k]
__global__ void fold_b2(const float* __restrict__ b2,
                        const float* __restrict__ W,
                        float* __restrict__ b2p)
{
    const int p = blockIdx.x * 256 + threadIdx.x;
    const int i = p >> 6, j = p & 63;
    float s = 0.0f;
    for (int k = 0; k < 64; ++k)
        s = fmaf(__ldg(&b2[i * 64 + k]), __ldg(&W[j * 64 + k]), s);
    b2p[p] = s;
}

// ---------------------------------------------------------------------------
// Per-sample: out_b = Ft_b @ Xp_b @ Ft_b^T,  Xp = [[x,0],[0,I16]]  (in-place)
// ---------------------------------------------------------------------------
__global__ __launch_bounds__(256)
void spd_out(const float* __restrict__ X, float* __restrict__ F)
{
    __shared__ float Fs[64 * 65];
    __shared__ float Xs[48 * 49];
    __shared__ float Gs[64 * 64];

    const int b = blockIdx.x;
    const int tid = threadIdx.x;

    const float* Fg = F + (long long)b * 4096;
    for (int p = tid; p < 4096; p += 256)
        Fs[(p >> 6) * 65 + (p & 63)] = Fg[p];
    const float* Xg = X + (long long)b * 2304;
    for (int p = tid; p < 2304; p += 256)
        Xs[(p / 48) * 49 + (p % 48)] = Xg[p];
    __syncthreads();

    const int tx = tid & 15, ty = tid >> 4;
    const int i0 = ty * 4, k0 = tx * 4;

    float g[4][4] = {};
    if (tx < 12) {
        for (int j = 0; j < 48; ++j) {
            float a[4], xb[4];
#pragma unroll
            for (int u = 0; u < 4; ++u) a[u]  = Fs[(i0 + u) * 65 + j];
#pragma unroll
            for (int u = 0; u < 4; ++u) xb[u] = Xs[j * 49 + k0 + u];
#pragma unroll
            for (int u = 0; u < 4; ++u)
#pragma unroll
                for (int v = 0; v < 4; ++v) g[u][v] = fmaf(a[u], xb[v], g[u][v]);
        }
    } else {
#pragma unroll
        for (int u = 0; u < 4; ++u)
#pragma unroll
            for (int v = 0; v < 4; ++v) g[u][v] = Fs[(i0 + u) * 65 + k0 + v];
    }
#pragma unroll
    for (int u = 0; u < 4; ++u)
#pragma unroll
        for (int v = 0; v < 4; ++v) Gs[(i0 + u) * 64 + k0 + v] = g[u][v];
    __syncthreads();

    const int l0 = tx * 4;
    float acc[4][4] = {};
    for (int k = 0; k < 64; ++k) {
        float a[4], bb[4];
#pragma unroll
        for (int u = 0; u < 4; ++u) a[u]  = Gs[(i0 + u) * 64 + k];
#pragma unroll
        for (int u = 0; u < 4; ++u) bb[u] = Fs[(l0 + u) * 65 + k];
#pragma unroll
        for (int u = 0; u < 4; ++u)
#pragma unroll
            for (int v = 0; v < 4; ++v) acc[u][v] = fmaf(a[u], bb[v], acc[u][v]);
    }

    float* Og = F + (long long)b * 4096;
#pragma unroll
    for (int u = 0; u < 4; ++u) {
        float4 o = make_float4(acc[u][0], acc[u][1], acc[u][2], acc[u][3]);
        *(float4*)&Og[(i0 + u) * 64 + l0] = o;
    }
}

// ---------------------------------------------------------------------------
extern "C" void kernel_launch(void* const* d_in, const int* in_sizes, int n_in,
                              void* d_out, int out_size)
{
    const float* x  = (const float*)d_in[0];  // [4096,48,48]
    const float* Y  = (const float*)d_in[2];  // [4096,64]
    const float* W  = (const float*)d_in[3];  // [64,64]
    const float* W1 = (const float*)d_in[4];  // [64,4096]
    const float* b1 = (const float*)d_in[5];  // [4096]
    const float* W2 = (const float*)d_in[6];  // [4096,4096]
    const float* b2 = (const float*)d_in[7];  // [4096]
    float* out = (float*)d_out;               // [4096,64,64]

    __nv_bfloat16 *ahi, *alo, *bhi, *blo;
    float* b2p;
    cudaGetSymbolAddress((void**)&ahi, g_Ahi);
    cudaGetSymbolAddress((void**)&alo, g_Alo);
    cudaGetSymbolAddress((void**)&bhi, g_Bhi);
    cudaGetSymbolAddress((void**)&blo, g_Blo);
    cudaGetSymbolAddress((void**)&b2p, g_b2p);

    cudaFuncSetAttribute(gemm_mma, cudaFuncAttributeMaxDynamicSharedMemorySize,
                         GTC_SMEM);

    fold_w2t<<<dim3(64, 64), 256>>>(W2, W, bhi, blo);
    fold_b2<<<16, 256>>>(b2, W, b2p);
    gemm_h<<<dim3(32, 32), 256>>>(Y, W1, b1, ahi, alo, 64, 4096);
    gemm_mma<<<dim3(16, 32), 256, GTC_SMEM>>>(ahi, alo, bhi, blo, b2p, out);
    spd_out<<<4096, 256>>>(x, out);
}

// round 10
// speedup vs baseline: 2.0133x; 1.1037x over previous
#include <cuda_runtime.h>
#include <cuda_bf16.h>
#include <math.h>
#include <stdint.h>

// ---------------------------------------------------------------------------
// SPDTransform, base-target tensor path (mma.sync bf16):
//   W2t'[n,k] = (W2 @ blockdiag(W))^T folded  -> bf16 hi/lo  [N=4096,K=4096]
//   h  = silu(Y@W1+b1)                        -> bf16 hi/lo  [M=4096,K=4096]
//   Ft = h @ W2'^T + b2'  via 3-product bf16-split mma.sync -> d_out fp32
//   out_b = Ft_b @ Xp_b @ Ft_b^T   (per-sample, Xp = [[x,0],[0,I16]])
// ---------------------------------------------------------------------------

__device__ __nv_bfloat16 g_Ahi[16777216];
__device__ __nv_bfloat16 g_Alo[16777216];
__device__ __nv_bfloat16 g_Bhi[16777216];
__device__ __nv_bfloat16 g_Blo[16777216];
__device__ float         g_b2p[4096];

__device__ __forceinline__ uint32_t smem_u32(const void* p) {
    uint32_t a;
    asm("{ .reg .u64 t; cvta.to.shared.u64 t, %1; cvt.u32.u64 %0, t; }"
        : "=r"(a) : "l"(p));
    return a;
}
__device__ __forceinline__ void cpa16(uint32_t d, const void* s) {
    asm volatile("cp.async.cg.shared.global [%0], [%1], 16;" :: "r"(d), "l"(s)
                 : "memory");
}
__device__ __forceinline__ void ldmx4(uint32_t* r, uint32_t a) {
    asm volatile("ldmatrix.sync.aligned.m8n8.x4.shared.b16 {%0,%1,%2,%3}, [%4];"
                 : "=r"(r[0]), "=r"(r[1]), "=r"(r[2]), "=r"(r[3]) : "r"(a));
}
__device__ __forceinline__ void mma16816(float* c, const uint32_t* a,
                                         uint32_t b0, uint32_t b1) {
    asm volatile(
        "mma.sync.aligned.m16n8k16.row.col.f32.bf16.bf16.f32 "
        "{%0,%1,%2,%3}, {%4,%5,%6,%7}, {%8,%9}, {%0,%1,%2,%3};"
        : "+f"(c[0]), "+f"(c[1]), "+f"(c[2]), "+f"(c[3])
        : "r"(a[0]), "r"(a[1]), "r"(a[2]), "r"(a[3]), "r"(b0), "r"(b1));
}

// Tile 128x128, BK=64 (row = 128 bytes).
// stage layout (bytes): Ahi 16K | Alo 16K | Bhi 16K | Blo 16K = 64K
static constexpr int ST_ALO = 16384;
static constexpr int ST_BHI = 32768;
static constexpr int ST_BLO = 49152;
static constexpr int STAGE  = 65536;
static constexpr int STAGES = 3;
static constexpr int GTC_SMEM = STAGES * STAGE;   // 192 KB

// ---------------------------------------------------------------------------
// C[M=4096, N=4096] = A @ B^T (+bias), A[M,K],B[N,K] bf16 hi/lo, K=4096.
// 3-product split: AhBh + AlBh + AhBl, fp32 accum.
// Tile 128x128, BK=64, 512 thr, 16 warps of 32x32 (4 per SMSP).
// 3-stage cp.async pipeline, single __syncthreads per k-chunk.
// grid (32 n, 32 m).
// ---------------------------------------------------------------------------
__global__ __launch_bounds__(512, 1)
void gemm_mma(const __nv_bfloat16* __restrict__ Ahi, const __nv_bfloat16* __restrict__ Alo,
              const __nv_bfloat16* __restrict__ Bhi, const __nv_bfloat16* __restrict__ Blo,
              const float* __restrict__ bias, float* __restrict__ C)
{
    extern __shared__ char dsm[];
    const uint32_t base = smem_u32(dsm);

    const int tid  = threadIdx.x;
    const int lane = tid & 31;
    const int wid  = tid >> 5;
    const int warp_m = wid & 3;             // 0..3  -> 32 rows
    const int warp_n = wid >> 2;            // 0..3  -> 32 cols
    const int m0 = blockIdx.y * 128;
    const int n0 = blockIdx.x * 128;

    // swizzle: row r (128B), logical 16B seg s (0..7) -> phys seg s ^ (r&7)
    auto load_stage = [&](int kt, int s) {
        const uint32_t sb = base + s * STAGE;
        const int kc = kt * 64;
#pragma unroll
        for (int it = 0; it < 2; ++it) {
            const int idx = tid + it * 512;          // 0..1023
            const int r = idx >> 3, sg = idx & 7;
            const uint32_t d = (uint32_t)(r * 128 + ((sg ^ (r & 7)) << 4));
            const size_t goA = (size_t)(m0 + r) * 4096 + kc + sg * 8;
            const size_t goB = (size_t)(n0 + r) * 4096 + kc + sg * 8;
            cpa16(sb + d,          Ahi + goA);
            cpa16(sb + ST_ALO + d, Alo + goA);
            cpa16(sb + ST_BHI + d, Bhi + goB);
            cpa16(sb + ST_BLO + d, Blo + goB);
        }
        asm volatile("cp.async.commit_group;" ::: "memory");
    };

    load_stage(0, 0);
    load_stage(1, 1);

    float acc[2][4][4];
#pragma unroll
    for (int i = 0; i < 2; ++i)
#pragma unroll
        for (int j = 0; j < 4; ++j)
#pragma unroll
            for (int v = 0; v < 4; ++v) acc[i][j][v] = 0.0f;

    const int rA0 = warp_m * 32 + (lane & 15);
    const int rB0 = warp_n * 32 + (lane & 15);
    const int shi = lane >> 4;                    // 16B seg within k16
    const int swz = (lane & 15) & 7;              // row-derived xor

    int sidx = 0;
#pragma unroll 1
    for (int kt = 0; kt < 64; ++kt) {
        asm volatile("cp.async.wait_group 1;" ::: "memory");
        __syncthreads();   // stage kt visible; all warps done with stage kt-1

        if (kt + 2 < 64) {
            int ps = sidx + 2; if (ps >= 3) ps -= 3;
            load_stage(kt + 2, ps);               // overwrites stage of kt-1
        }

        const uint32_t sb = base + sidx * STAGE;
#pragma unroll
        for (int ks = 0; ks < 4; ++ks) {
            const int slog = ks * 2 + shi;
            const uint32_t segoff = (uint32_t)(((slog ^ swz) & 7) << 4);
            uint32_t ah[2][4], al[2][4], bh[2][4], bl[2][4];
#pragma unroll
            for (int mt = 0; mt < 2; ++mt) {
                const uint32_t off = (uint32_t)((rA0 + mt * 16) * 128) + segoff;
                ldmx4(ah[mt], sb + off);
                ldmx4(al[mt], sb + ST_ALO + off);
            }
#pragma unroll
            for (int bt = 0; bt < 2; ++bt) {
                const uint32_t off = (uint32_t)((rB0 + bt * 16) * 128) + segoff;
                ldmx4(bh[bt], sb + ST_BHI + off);
                ldmx4(bl[bt], sb + ST_BLO + off);
            }
#pragma unroll
            for (int mt = 0; mt < 2; ++mt)
#pragma unroll
                for (int nt = 0; nt < 4; ++nt) {
                    const uint32_t h0 = bh[nt >> 1][nt & 1];
                    const uint32_t h1 = bh[nt >> 1][(nt & 1) + 2];
                    mma16816(acc[mt][nt], ah[mt], h0, h1);
                    mma16816(acc[mt][nt], al[mt], h0, h1);
                    mma16816(acc[mt][nt], ah[mt],
                             bl[nt >> 1][nt & 1], bl[nt >> 1][(nt & 1) + 2]);
                }
        }
        ++sidx; if (sidx >= 3) sidx = 0;
    }

    // epilogue: c frag lane l -> rows l/4, l/4+8; cols 2*(l&3)+{0,1}
#pragma unroll
    for (int mt = 0; mt < 2; ++mt)
#pragma unroll
        for (int nt = 0; nt < 4; ++nt) {
            const float* c = acc[mt][nt];
            const int row = m0 + warp_m * 32 + mt * 16 + (lane >> 2);
            const int col = n0 + warp_n * 32 + nt * 8 + 2 * (lane & 3);
            const float bv0 = __ldg(&bias[col]);
            const float bv1 = __ldg(&bias[col + 1]);
            float2 o0 = make_float2(c[0] + bv0, c[1] + bv1);
            float2 o1 = make_float2(c[2] + bv0, c[3] + bv1);
            *(float2*)(C + (size_t)row * 4096 + col)       = o0;
            *(float2*)(C + (size_t)(row + 8) * 4096 + col) = o1;
        }
}

// ---------------------------------------------------------------------------
// h = silu(Y @ W1 + b1), emitted as bf16 hi/lo. FFMA kernel (K=64, tiny).
// ---------------------------------------------------------------------------
__global__ __launch_bounds__(256, 2)
void gemm_h(const float* __restrict__ A, const float* __restrict__ B,
            const float* __restrict__ bias,
            __nv_bfloat16* __restrict__ Chi, __nv_bfloat16* __restrict__ Clo,
            int K, int N)
{
    __shared__ __align__(16) float As[2][16][132];
    __shared__ __align__(16) float Bs[2][16][128];

    const int tid = threadIdx.x;
    const int tx = tid & 15, ty = tid >> 4;
    const long long Arow0 = (long long)blockIdx.y * 128;
    const int Bcol0 = blockIdx.x * 128;

    const int arow = tid >> 2, ac = (tid & 3) << 2;
    const int brow = tid >> 5, bc = (tid & 31) << 2;

    const float* Aptr = A + (Arow0 + arow) * (long long)K + ac;
    const float* Bptr = B + (long long)brow * N + Bcol0 + bc;
    const long long AstepRow = 64LL * K;
    const long long BstepRow = 8LL * N;

    float acc[8][8] = {};
    const int nk = K >> 4;

    float4 a0 = *(const float4*)(Aptr);
    float4 a1 = *(const float4*)(Aptr + AstepRow);
    float4 b0 = *(const float4*)(Bptr);
    float4 b1 = *(const float4*)(Bptr + BstepRow);

    int buf = 0;
    As[0][ac + 0][arow] = a0.x; As[0][ac + 1][arow] = a0.y;
    As[0][ac + 2][arow] = a0.z; As[0][ac + 3][arow] = a0.w;
    As[0][ac + 0][arow + 64] = a1.x; As[0][ac + 1][arow + 64] = a1.y;
    As[0][ac + 2][arow + 64] = a1.z; As[0][ac + 3][arow + 64] = a1.w;
    *(float4*)&Bs[0][brow][bc]     = b0;
    *(float4*)&Bs[0][brow + 8][bc] = b1;
    __syncthreads();

    for (int kt = 1; kt <= nk; ++kt) {
        if (kt < nk) {
            const float* Ap = Aptr + kt * 16;
            a0 = *(const float4*)(Ap);
            a1 = *(const float4*)(Ap + AstepRow);
            const float* Bp = Bptr + (long long)kt * 16 * N;
            b0 = *(const float4*)(Bp);
            b1 = *(const float4*)(Bp + BstepRow);
        }
#pragma unroll
        for (int k = 0; k < 16; ++k) {
            float av[8], bv[8];
            *(float4*)&av[0] = *(const float4*)&As[buf][k][ty * 8];
            *(float4*)&av[4] = *(const float4*)&As[buf][k][ty * 8 + 4];
            *(float4*)&bv[0] = *(const float4*)&Bs[buf][k][tx * 8];
            *(float4*)&bv[4] = *(const float4*)&Bs[buf][k][tx * 8 + 4];
#pragma unroll
            for (int i = 0; i < 8; ++i)
#pragma unroll
                for (int j = 0; j < 8; ++j)
                    acc[i][j] = fmaf(av[i], bv[j], acc[i][j]);
        }
        if (kt < nk) {
            const int nb = buf ^ 1;
            As[nb][ac + 0][arow] = a0.x; As[nb][ac + 1][arow] = a0.y;
            As[nb][ac + 2][arow] = a0.z; As[nb][ac + 3][arow] = a0.w;
            As[nb][ac + 0][arow + 64] = a1.x; As[nb][ac + 1][arow + 64] = a1.y;
            As[nb][ac + 2][arow + 64] = a1.z; As[nb][ac + 3][arow + 64] = a1.w;
            *(float4*)&Bs[nb][brow][bc]     = b0;
            *(float4*)&Bs[nb][brow + 8][bc] = b1;
        }
        __syncthreads();
        buf ^= 1;
    }

    const int col0 = Bcol0 + tx * 8;
#pragma unroll
    for (int i = 0; i < 8; ++i) {
        const long long row = Arow0 + ty * 8 + i;
        union { __nv_bfloat16 h[8]; uint4 u; } ph, pl;
#pragma unroll
        for (int j = 0; j < 8; ++j) {
            float v = acc[i][j] + __ldg(&bias[col0 + j]);
            v = v / (1.0f + expf(-v));                 // silu
            __nv_bfloat16 hi = __float2bfloat16(v);
            ph.h[j] = hi;
            pl.h[j] = __float2bfloat16(v - __bfloat162float(hi));
        }
        *(uint4*)&Chi[row * N + col0] = ph.u;
        *(uint4*)&Clo[row * N + col0] = pl.u;
    }
}

// ---------------------------------------------------------------------------
// Fold + transpose: B[n=64i+j, k=m] = sum_t W2[m,64i+t] * W[j*64+t], bf16 hi/lo
// ---------------------------------------------------------------------------
__global__ __launch_bounds__(256)
void fold_w2t(const float* __restrict__ W2, const float* __restrict__ W,
              __nv_bfloat16* __restrict__ Bhi, __nv_bfloat16* __restrict__ Blo)
{
    __shared__ float W2s[64][65];
    __shared__ float Ws[64][64];
    const int i = blockIdx.x;
    const int m0 = blockIdx.y * 64;
    const int tid = threadIdx.x;

    for (int p = tid; p < 4096; p += 256) {
        const int mm = p >> 6, k = p & 63;
        W2s[mm][k] = W2[(size_t)(m0 + mm) * 4096 + i * 64 + k];
    }
    for (int p = tid; p < 4096; p += 256) Ws[p >> 6][p & 63] = W[p];
    __syncthreads();

    const int mm = tid & 63, jg = tid >> 6;
#pragma unroll 1
    for (int jj = 0; jj < 16; ++jj) {
        const int j = jg * 16 + jj;
        float acc = 0.0f;
#pragma unroll
        for (int k = 0; k < 64; ++k) acc = fmaf(W2s[mm][k], Ws[j][k], acc);
        const size_t o = (size_t)(i * 64 + j) * 4096 + m0 + mm;
        __nv_bfloat16 hi = __float2bfloat16(acc);
        Bhi[o] = hi;
        Blo[o] = __float2bfloat16(acc - __bfloat162float(hi));
    }
}

// b2'[64i+j] = sum_k b2[64i+k] * W[j*64+k]
__global__ void fold_b2(const float* __restrict__ b2,
                        const float* __restrict__ W,
                        float* __restrict__ b2p)
{
    const int p = blockIdx.x * 256 + threadIdx.x;
    const int i = p >> 6, j = p & 63;
    float s = 0.0f;
    for (int k = 0; k < 64; ++k)
        s = fmaf(__ldg(&b2[i * 64 + k]), __ldg(&W[j * 64 + k]), s);
    b2p[p] = s;
}

// ---------------------------------------------------------------------------
// Per-sample: out_b = Ft_b @ Xp_b @ Ft_b^T,  Xp = [[x,0],[0,I16]]  (in-place)
// ---------------------------------------------------------------------------
__global__ __launch_bounds__(256)
void spd_out(const float* __restrict__ X, float* __restrict__ F)
{
    __shared__ float Fs[64 * 65];
    __shared__ float Xs[48 * 49];
    __shared__ float Gs[64 * 64];

    const int b = blockIdx.x;
    const int tid = threadIdx.x;

    const float* Fg = F + (long long)b * 4096;
    for (int p = tid; p < 4096; p += 256)
        Fs[(p >> 6) * 65 + (p & 63)] = Fg[p];
    const float* Xg = X + (long long)b * 2304;
    for (int p = tid; p < 2304; p += 256)
        Xs[(p / 48) * 49 + (p % 48)] = Xg[p];
    __syncthreads();

    const int tx = tid & 15, ty = tid >> 4;
    const int i0 = ty * 4, k0 = tx * 4;

    float g[4][4] = {};
    if (tx < 12) {
        for (int j = 0; j < 48; ++j) {
            float a[4], xb[4];
#pragma unroll
            for (int u = 0; u < 4; ++u) a[u]  = Fs[(i0 + u) * 65 + j];
#pragma unroll
            for (int u = 0; u < 4; ++u) xb[u] = Xs[j * 49 + k0 + u];
#pragma unroll
            for (int u = 0; u < 4; ++u)
#pragma unroll
                for (int v = 0; v < 4; ++v) g[u][v] = fmaf(a[u], xb[v], g[u][v]);
        }
    } else {
#pragma unroll
        for (int u = 0; u < 4; ++u)
#pragma unroll
            for (int v = 0; v < 4; ++v) g[u][v] = Fs[(i0 + u) * 65 + k0 + v];
    }
#pragma unroll
    for (int u = 0; u < 4; ++u)
#pragma unroll
        for (int v = 0; v < 4; ++v) Gs[(i0 + u) * 64 + k0 + v] = g[u][v];
    __syncthreads();

    const int l0 = tx * 4;
    float acc[4][4] = {};
    for (int k = 0; k < 64; ++k) {
        float a[4], bb[4];
#pragma unroll
        for (int u = 0; u < 4; ++u) a[u]  = Gs[(i0 + u) * 64 + k];
#pragma unroll
        for (int u = 0; u < 4; ++u) bb[u] = Fs[(l0 + u) * 65 + k];
#pragma unroll
        for (int u = 0; u < 4; ++u)
#pragma unroll
            for (int v = 0; v < 4; ++v) acc[u][v] = fmaf(a[u], bb[v], acc[u][v]);
    }

    float* Og = F + (long long)b * 4096;
#pragma unroll
    for (int u = 0; u < 4; ++u) {
        float4 o = make_float4(acc[u][0], acc[u][1], acc[u][2], acc[u][3]);
        *(float4*)&Og[(i0 + u) * 64 + l0] = o;
    }
}

// ---------------------------------------------------------------------------
extern "C" void kernel_launch(void* const* d_in, const int* in_sizes, int n_in,
                              void* d_out, int out_size)
{
    const float* x  = (const float*)d_in[0];  // [4096,48,48]
    const float* Y  = (const float*)d_in[2];  // [4096,64]
    const float* W  = (const float*)d_in[3];  // [64,64]
    const float* W1 = (const float*)d_in[4];  // [64,4096]
    const float* b1 = (const float*)d_in[5];  // [4096]
    const float* W2 = (const float*)d_in[6];  // [4096,4096]
    const float* b2 = (const float*)d_in[7];  // [4096]
    float* out = (float*)d_out;               // [4096,64,64]

    __nv_bfloat16 *ahi, *alo, *bhi, *blo;
    float* b2p;
    cudaGetSymbolAddress((void**)&ahi, g_Ahi);
    cudaGetSymbolAddress((void**)&alo, g_Alo);
    cudaGetSymbolAddress((void**)&bhi, g_Bhi);
    cudaGetSymbolAddress((void**)&blo, g_Blo);
    cudaGetSymbolAddress((void**)&b2p, g_b2p);

    cudaFuncSetAttribute(gemm_mma, cudaFuncAttributeMaxDynamicSharedMemorySize,
                         GTC_SMEM);

    fold_w2t<<<dim3(64, 64), 256>>>(W2, W, bhi, blo);
    fold_b2<<<16, 256>>>(b2, W, b2p);
    gemm_h<<<dim3(32, 32), 256>>>(Y, W1, b1, ahi, alo, 64, 4096);
    gemm_mma<<<dim3(32, 32), 512, GTC_SMEM>>>(ahi, alo, bhi, blo, b2p, out);
    spd_out<<<4096, 256>>>(x, out);
}